// round 14
// baseline (speedup 1.0000x reference)
#include <cuda_runtime.h>
#include <cuda_bf16.h>
#include <math.h>
#include <stdint.h>

#define SS 1024
#define DD 128
#define NBH 24
#define NH 12

// scratch: scores (raw QK^T, lower-triangle tiles only)
__device__ float g_scores[(size_t)NBH * SS * SS];
// pre-split V planes (bf16 hi/lo), 16B-aligned for uint4 vector access
__device__ __align__(16) __nv_bfloat16 g_vh[(size_t)NBH * SS * DD];
__device__ __align__(16) __nv_bfloat16 g_vl[(size_t)NBH * SS * DD];
// split-K partials: unnormalized O and row sums, up to 4 splits per q-tile
__device__ float g_opart[4][(size_t)NBH * SS * DD];
__device__ float g_spart[4][NBH * SS];

// CTA -> (q-tile, split) map: q-tile qt has ceil((qt+1)/4) splits of <=4 chunks
__device__ const int8_t c_qt[40] = {0,1,2,3, 4,4, 5,5, 6,6, 7,7,
                                    8,8,8, 9,9,9, 10,10,10, 11,11,11,
                                    12,12,12,12, 13,13,13,13, 14,14,14,14, 15,15,15,15};
__device__ const int8_t c_sp[40] = {0,0,0,0, 0,1, 0,1, 0,1, 0,1,
                                    0,1,2, 0,1,2, 0,1,2, 0,1,2,
                                    0,1,2,3, 0,1,2,3, 0,1,2,3, 0,1,2,3};

__device__ __forceinline__ uint32_t smem_u32(const void* p) {
    uint32_t a;
    asm("{ .reg .u64 t; cvta.to.shared.u64 t, %1; cvt.u32.u64 %0, t; }"
        : "=r"(a) : "l"(p));
    return a;
}

#define LDMATRIX_X4(r0, r1, r2, r3, addr) \
    asm volatile("ldmatrix.sync.aligned.m8n8.x4.shared.b16 {%0,%1,%2,%3}, [%4];" \
                 : "=r"(r0), "=r"(r1), "=r"(r2), "=r"(r3) : "r"(addr))

#define LDMATRIX_X4_T(r0, r1, r2, r3, addr) \
    asm volatile("ldmatrix.sync.aligned.m8n8.x4.trans.shared.b16 {%0,%1,%2,%3}, [%4];" \
                 : "=r"(r0), "=r"(r1), "=r"(r2), "=r"(r3) : "r"(addr))

#define MMA_BF16(d, a, b) \
    asm volatile("mma.sync.aligned.m16n8k16.row.col.f32.bf16.bf16.f32 " \
                 "{%0,%1,%2,%3}, {%4,%5,%6,%7}, {%8,%9}, {%0,%1,%2,%3};" \
                 : "+f"((d)[0]), "+f"((d)[1]), "+f"((d)[2]), "+f"((d)[3]) \
                 : "r"((a)[0]), "r"((a)[1]), "r"((a)[2]), "r"((a)[3]), \
                   "r"((b)[0]), "r"((b)[1]))

// packed f32x2 helpers (Blackwell FFMA2 path), b32-register constraints
__device__ __forceinline__ unsigned long long pack2(float lo, float hi) {
    unsigned long long r;
    asm("mov.b64 %0, {%1, %2};" : "=l"(r)
        : "r"(__float_as_uint(lo)), "r"(__float_as_uint(hi)));
    return r;
}
#define FMA2(acc, a, b) \
    asm("fma.rn.f32x2 %0, %1, %2, %0;" : "+l"(acc) : "l"(a), "l"(b))
__device__ __forceinline__ void unpack2(unsigned long long v, float& lo, float& hi) {
    uint32_t a, b;
    asm("mov.b64 {%0, %1}, %2;" : "=r"(a), "=r"(b) : "l"(v));
    lo = __uint_as_float(a);
    hi = __uint_as_float(b);
}

// fast exp on the FMA pipe
__device__ __forceinline__ float fexp(float x) {
    float y = x * 1.4426950408889634f;
    y = fminf(fmaxf(y, -120.f), 120.f);
    float fy = floorf(y);
    float f = y - fy;
    float p = 1.5403530e-4f;
    p = fmaf(p, f, 1.3333558e-3f);
    p = fmaf(p, f, 9.6181291e-3f);
    p = fmaf(p, f, 5.5504109e-2f);
    p = fmaf(p, f, 2.4022651e-1f);
    p = fmaf(p, f, 6.9314718e-1f);
    p = fmaf(p, f, 1.0f);
    int e = (int)fy;
    return p * __int_as_float((e + 127) << 23);
}

__device__ __forceinline__ void split_store4(__nv_bfloat16* hi, __nv_bfloat16* lo, float4 v) {
    __nv_bfloat16 h0 = __float2bfloat16(v.x), h1 = __float2bfloat16(v.y);
    __nv_bfloat16 h2 = __float2bfloat16(v.z), h3 = __float2bfloat16(v.w);
    __nv_bfloat162 hp0(h0, h1), hp1(h2, h3);
    __nv_bfloat162 lp0 = __floats2bfloat162_rn(v.x - __bfloat162float(h0),
                                               v.y - __bfloat162float(h1));
    __nv_bfloat162 lp1 = __floats2bfloat162_rn(v.z - __bfloat162float(h2),
                                               v.w - __bfloat162float(h3));
    *(uint2*)hi = make_uint2(*(uint32_t*)&hp0, *(uint32_t*)&hp1);
    *(uint2*)lo = make_uint2(*(uint32_t*)&lp0, *(uint32_t*)&lp1);
}

// ---------------------------------------------------------------------------
// Kernel 0: pre-split V into bf16 hi/lo planes (done once, reused 8.5x)
// ---------------------------------------------------------------------------
__global__ __launch_bounds__(256) void vsplit_prep(const float* __restrict__ V)
{
    const size_t i = ((size_t)blockIdx.x * 256 + threadIdx.x) * 4;
    float4 v = *(const float4*)&V[i];
    split_store4(&g_vh[i], &g_vl[i], v);
}

// ---------------------------------------------------------------------------
// Kernel 1: scores = Q @ K^T via mma.sync bf16 split (3 terms)
// ---------------------------------------------------------------------------
#define LDE2 72
#define PLANE2 (128 * LDE2)

__global__ __launch_bounds__(256, 2) void qk_gemm_mma(
    const float* __restrict__ Q, const float* __restrict__ K)
{
    const int kt = blockIdx.x;
    const int qt = blockIdx.y;
    if (kt > qt) return;
    const int bh = blockIdx.z;

    extern __shared__ __align__(16) __nv_bfloat16 smem[];
    __nv_bfloat16* QH = smem;
    __nv_bfloat16* QL = smem + PLANE2;
    __nv_bfloat16* KH = smem + 2 * PLANE2;
    __nv_bfloat16* KL = smem + 3 * PLANE2;

    const int tid = threadIdx.x;
    const float* Qb = Q + ((size_t)bh * SS + (size_t)qt * 128) * DD;
    const float* Kb = K + ((size_t)bh * SS + (size_t)kt * 128) * DD;

    const int warp = tid >> 5, lane = tid & 31;
    const int m0 = (warp & 3) * 32;
    const int n0 = (warp >> 2) * 64;
    const int lrow = lane & 15;
    const int lgrp = lane >> 4;

    float acc[2][8][4] = {};

    for (int half = 0; half < 2; half++) {
        if (half) __syncthreads();
        for (int i = tid; i < 128 * 16; i += 256) {
            const int row = i >> 4, k = (i & 15) * 4;
            float4 v = *(const float4*)&Qb[(size_t)row * DD + half * 64 + k];
            split_store4(&QH[row * LDE2 + k], &QL[row * LDE2 + k], v);
            float4 u = *(const float4*)&Kb[(size_t)row * DD + half * 64 + k];
            split_store4(&KH[row * LDE2 + k], &KL[row * LDE2 + k], u);
        }
        __syncthreads();

        #pragma unroll
        for (int ks = 0; ks < 4; ks++) {
            const int kb = ks * 16;
            uint32_t ah[2][4], al[2][4];
            #pragma unroll
            for (int mi = 0; mi < 2; mi++) {
                uint32_t aH = smem_u32(&QH[(m0 + mi * 16 + lrow) * LDE2 + kb + lgrp * 8]);
                LDMATRIX_X4(ah[mi][0], ah[mi][1], ah[mi][2], ah[mi][3], aH);
                uint32_t aL = smem_u32(&QL[(m0 + mi * 16 + lrow) * LDE2 + kb + lgrp * 8]);
                LDMATRIX_X4(al[mi][0], al[mi][1], al[mi][2], al[mi][3], aL);
            }
            #pragma unroll
            for (int nfi = 0; nfi < 4; nfi++) {
                uint32_t bh4[4], bl4[4];
                uint32_t bHaddr = smem_u32(&KH[(n0 + nfi * 16 + lrow) * LDE2 + kb + lgrp * 8]);
                LDMATRIX_X4(bh4[0], bh4[1], bh4[2], bh4[3], bHaddr);
                uint32_t bLaddr = smem_u32(&KL[(n0 + nfi * 16 + lrow) * LDE2 + kb + lgrp * 8]);
                LDMATRIX_X4(bl4[0], bl4[1], bl4[2], bl4[3], bLaddr);

                uint32_t bh0[2] = {bh4[0], bh4[2]}, bh1[2] = {bh4[1], bh4[3]};
                uint32_t bl0[2] = {bl4[0], bl4[2]}, bl1[2] = {bl4[1], bl4[3]};

                #pragma unroll
                for (int mi = 0; mi < 2; mi++) {
                    MMA_BF16(acc[mi][2 * nfi],     ah[mi], bh0);
                    MMA_BF16(acc[mi][2 * nfi],     ah[mi], bl0);
                    MMA_BF16(acc[mi][2 * nfi],     al[mi], bh0);
                    MMA_BF16(acc[mi][2 * nfi + 1], ah[mi], bh1);
                    MMA_BF16(acc[mi][2 * nfi + 1], ah[mi], bl1);
                    MMA_BF16(acc[mi][2 * nfi + 1], al[mi], bh1);
                }
            }
        }
    }

    float* out = g_scores + (size_t)bh * SS * SS;
    const int g = lane >> 2, t2 = (lane & 3) * 2;
    #pragma unroll
    for (int mi = 0; mi < 2; mi++) {
        const int r1 = qt * 128 + m0 + mi * 16 + g;
        const int r2 = r1 + 8;
        #pragma unroll
        for (int nf = 0; nf < 8; nf++) {
            const int col = kt * 128 + n0 + nf * 8 + t2;
            *(float2*)&out[(size_t)r1 * SS + col] = make_float2(acc[mi][nf][0], acc[mi][nf][1]);
            *(float2*)&out[(size_t)r2 * SS + col] = make_float2(acc[mi][nf][2], acc[mi][nf][3]);
        }
    }
}

// ---------------------------------------------------------------------------
// Kernel 2 (fused, split-K balanced): conv (f32x2 packed) + exp + P@V partial.
// V staged from pre-split hi/lo planes.
// ---------------------------------------------------------------------------
#define PV_LDP 72    // P plane stride (bf16)
#define PV_LDV 136   // V plane stride (bf16)
#define S_LD 76      // score halo tile stride (float)

__global__ __launch_bounds__(256, 2) void conv_softmax_pv(const float* __restrict__ W)
{
    const int ent = blockIdx.x;       // 0..39
    const int bh = blockIdx.y;
    const int qt = c_qt[ent];
    const int sp = c_sp[ent];
    const int q0 = qt * 64;
    const int c0 = sp * 4;
    const int c1 = min(qt + 1, c0 + 4);

    const float* Sb = g_scores + (size_t)bh * SS * SS;
    const __nv_bfloat16* gvh = g_vh + (size_t)bh * SS * DD;
    const __nv_bfloat16* gvl = g_vl + (size_t)bh * SS * DD;

    extern __shared__ __align__(16) char dsm[];
    float* Ssh = (float*)dsm;                           // 69 x 76
    __nv_bfloat16* Ph = (__nv_bfloat16*)(Ssh + 69 * S_LD);
    __nv_bfloat16* Pl = Ph + 64 * PV_LDP;
    __nv_bfloat16* Vh = Pl + 64 * PV_LDP;               // 64 x 136
    __nv_bfloat16* Vl = Vh + 64 * PV_LDV;
    unsigned long long* ws2 = (unsigned long long*)(Vl + 64 * PV_LDV);  // 66 pairs

    const int tid = threadIdx.x;
    const int warp = tid >> 5, lane = tid & 31;
    const int m0 = (warp & 1) * 32;
    const int n0 = (warp >> 1) * 32;

    const int h = bh % NH;
    if (tid < 66) {
        float w = W[h * 66 + tid];
        ws2[tid] = pack2(w, w);
    }

    const int pr = tid >> 2;            // 0..63 (fixed q-row)
    const int pc = (tid & 3) * 16;      // 0..48 (16-key segment)
    const int pq = q0 + pr;
    float psum = 0.f;

    float acc[2][4][4] = {};

    const int lrow = lane & 15;
    const int lgrp = lane >> 4;
    const int bi = lane >> 3;
    const int brow = lane & 7;

    const float scale = 0.088388347648318447f;  // 1/sqrt(128)

    for (int ch = c0; ch < c1; ch++) {
        const int kc = ch * 64;
        if (ch > c0) __syncthreads();

        // stage scores halo tile (causal-masked at load)
        for (int i = tid; i < 69 * 74; i += 256) {
            const int rr = i / 74, cc = i % 74;
            const int q = q0 - 5 + rr;
            const int k = kc - 5 + cc;
            float v = 0.f;
            if (q >= 0 && k >= 0 && k <= q) v = Sb[(size_t)q * SS + k];
            Ssh[rr * S_LD + cc] = v;
        }
        // stage pre-split V chunk: uint4 = 16B = 8 bf16 elements per copy;
        // 16 copies x 8 elems = full 128-element row.  (R11-13 bug: half-row)
        for (int i = tid; i < 64 * 16; i += 256) {
            const int kr = i >> 4, c8 = (i & 15) * 8;
            *(uint4*)&Vh[kr * PV_LDV + c8] =
                *(const uint4*)&gvh[(size_t)(kc + kr) * DD + c8];
            *(uint4*)&Vl[kr * PV_LDV + c8] =
                *(const uint4*)&gvl[(size_t)(kc + kr) * DD + c8];
        }
        __syncthreads();

        // conv via packed f32x2 -> scale -> exp -> split-bf16 P
        {
            unsigned long long acc2[8];
            #pragma unroll
            for (int p = 0; p < 8; p++) acc2[p] = 0ull;

            #pragma unroll
            for (int dq = 0; dq < 6; dq++) {
                const float* srow = &Ssh[(pr + dq) * S_LD + pc];
                unsigned long long win2[25];
                float4 a = *(const float4*)&srow[0];
                #pragma unroll
                for (int t = 0; t < 6; t++) {
                    float4 b = *(const float4*)&srow[(t + 1) * 4];
                    win2[4 * t + 0] = pack2(a.x, a.y);
                    win2[4 * t + 1] = pack2(a.y, a.z);
                    win2[4 * t + 2] = pack2(a.z, a.w);
                    win2[4 * t + 3] = pack2(a.w, b.x);
                    a = b;
                }
                win2[24] = pack2(a.x, a.y);

                #pragma unroll
                for (int dk = 0; dk < 11; dk++) {
                    unsigned long long w2 = ws2[dq * 11 + dk];
                    #pragma unroll
                    for (int p = 0; p < 8; p++) FMA2(acc2[p], w2, win2[2 * p + dk]);
                }
            }

            #pragma unroll
            for (int j4 = 0; j4 < 4; j4++) {
                float o0, o1, o2, o3;
                unpack2(acc2[2 * j4],     o0, o1);
                unpack2(acc2[2 * j4 + 1], o2, o3);
                const int kbase = kc + pc + j4 * 4;
                float e0 = (kbase + 0 <= pq) ? fexp(o0 * scale) : 0.f;
                float e1 = (kbase + 1 <= pq) ? fexp(o1 * scale) : 0.f;
                float e2 = (kbase + 2 <= pq) ? fexp(o2 * scale) : 0.f;
                float e3 = (kbase + 3 <= pq) ? fexp(o3 * scale) : 0.f;
                psum += (e0 + e1) + (e2 + e3);
                split_store4(&Ph[pr * PV_LDP + pc + j4 * 4],
                             &Pl[pr * PV_LDP + pc + j4 * 4],
                             make_float4(e0, e1, e2, e3));
            }
        }
        __syncthreads();

        // 3-term HMMA: acc += Phi*Vhi + Phi*Vlo + Plo*Vhi
        #pragma unroll
        for (int ks = 0; ks < 4; ks++) {
            const int kb = ks * 16;
            uint32_t ah[2][4], al[2][4];
            #pragma unroll
            for (int mi = 0; mi < 2; mi++) {
                uint32_t aH = smem_u32(&Ph[(m0 + mi * 16 + lrow) * PV_LDP + kb + lgrp * 8]);
                LDMATRIX_X4(ah[mi][0], ah[mi][1], ah[mi][2], ah[mi][3], aH);
                uint32_t aL = smem_u32(&Pl[(m0 + mi * 16 + lrow) * PV_LDP + kb + lgrp * 8]);
                LDMATRIX_X4(al[mi][0], al[mi][1], al[mi][2], al[mi][3], aL);
            }
            #pragma unroll
            for (int ng = 0; ng < 2; ng++) {
                const int vrow = kb + (bi & 1) * 8 + brow;
                const int vcol = n0 + ng * 16 + (bi >> 1) * 8;
                uint32_t bh4[4], bl4[4];
                uint32_t bHaddr = smem_u32(&Vh[vrow * PV_LDV + vcol]);
                LDMATRIX_X4_T(bh4[0], bh4[1], bh4[2], bh4[3], bHaddr);
                uint32_t bLaddr = smem_u32(&Vl[vrow * PV_LDV + vcol]);
                LDMATRIX_X4_T(bl4[0], bl4[1], bl4[2], bl4[3], bLaddr);

                uint32_t bh0[2] = {bh4[0], bh4[1]}, bh1[2] = {bh4[2], bh4[3]};
                uint32_t bl0[2] = {bl4[0], bl4[1]}, bl1[2] = {bl4[2], bl4[3]};

                #pragma unroll
                for (int mi = 0; mi < 2; mi++) {
                    MMA_BF16(acc[mi][2 * ng],     ah[mi], bh0);
                    MMA_BF16(acc[mi][2 * ng],     ah[mi], bl0);
                    MMA_BF16(acc[mi][2 * ng],     al[mi], bh0);
                    MMA_BF16(acc[mi][2 * ng + 1], ah[mi], bh1);
                    MMA_BF16(acc[mi][2 * ng + 1], ah[mi], bl1);
                    MMA_BF16(acc[mi][2 * ng + 1], al[mi], bh1);
                }
            }
        }
    }

    // partial row sums (quad lanes share row pr)
    psum += __shfl_xor_sync(0xffffffffu, psum, 1);
    psum += __shfl_xor_sync(0xffffffffu, psum, 2);
    if ((tid & 3) == 0) g_spart[sp][bh * SS + q0 + pr] = psum;

    // write unnormalized partial O
    float* Op = g_opart[sp] + (size_t)bh * SS * DD;
    const int g = lane >> 2, t2 = (lane & 3) * 2;
    #pragma unroll
    for (int mi = 0; mi < 2; mi++) {
        const int lr1 = m0 + mi * 16 + g;
        const int lr2 = lr1 + 8;
        #pragma unroll
        for (int nf = 0; nf < 4; nf++) {
            const int col = n0 + nf * 8 + t2;
            *(float2*)&Op[(size_t)(q0 + lr1) * DD + col] =
                make_float2(acc[mi][nf][0], acc[mi][nf][1]);
            *(float2*)&Op[(size_t)(q0 + lr2) * DD + col] =
                make_float2(acc[mi][nf][2], acc[mi][nf][3]);
        }
    }
}

// ---------------------------------------------------------------------------
// Kernel 3: reduce partials and normalize.  O = (sum_s Op_s) / (sum_s rowSum_s)
// ---------------------------------------------------------------------------
__global__ __launch_bounds__(256) void reduce_out(float* __restrict__ O)
{
    const int row = blockIdx.x * 8 + (threadIdx.x >> 5);
    const int lane = threadIdx.x & 31;
    const int q = row & (SS - 1);
    const int ns = ((q >> 6) >> 2) + 1;

    float s = g_spart[0][row];
    if (ns > 1) s += g_spart[1][row];
    if (ns > 2) s += g_spart[2][row];
    if (ns > 3) s += g_spart[3][row];
    const float inv = 1.f / s;

    const size_t base = (size_t)row * DD + lane * 4;
    float4 a = *(const float4*)&g_opart[0][base];
    if (ns > 1) {
        float4 v = *(const float4*)&g_opart[1][base];
        a.x += v.x; a.y += v.y; a.z += v.z; a.w += v.w;
    }
    if (ns > 2) {
        float4 v = *(const float4*)&g_opart[2][base];
        a.x += v.x; a.y += v.y; a.z += v.z; a.w += v.w;
    }
    if (ns > 3) {
        float4 v = *(const float4*)&g_opart[3][base];
        a.x += v.x; a.y += v.y; a.z += v.z; a.w += v.w;
    }
    *(float4*)&O[base] = make_float4(a.x * inv, a.y * inv, a.z * inv, a.w * inv);
}

// ---------------------------------------------------------------------------
extern "C" void kernel_launch(void* const* d_in, const int* in_sizes, int n_in,
                              void* d_out, int out_size)
{
    const float* Q = (const float*)d_in[0];
    const float* K = (const float*)d_in[1];
    const float* V = (const float*)d_in[2];
    const float* W = (const float*)d_in[3];
    float* O = (float*)d_out;

    const int QK_SMEM = 4 * PLANE2 * (int)sizeof(__nv_bfloat16);  // 73728 B
    cudaFuncSetAttribute(qk_gemm_mma, cudaFuncAttributeMaxDynamicSharedMemorySize, QK_SMEM);

    const int PV_SMEM = 69 * S_LD * (int)sizeof(float)
                      + (2 * 64 * PV_LDP + 2 * 64 * PV_LDV) * (int)sizeof(__nv_bfloat16)
                      + 66 * (int)sizeof(unsigned long long);     // ~74.8 KB
    cudaFuncSetAttribute(conv_softmax_pv, cudaFuncAttributeMaxDynamicSharedMemorySize, PV_SMEM);

    vsplit_prep<<<(NBH * SS * DD) / (256 * 4), 256>>>(V);

    dim3 g1(8, 8, NBH);
    qk_gemm_mma<<<g1, 256, QK_SMEM>>>(Q, K);

    dim3 g2(40, NBH);
    conv_softmax_pv<<<g2, 256, PV_SMEM>>>(W);

    reduce_out<<<NBH * SS / 8, 256>>>(O);
}

// round 15
// speedup vs baseline: 1.0415x; 1.0415x over previous
#include <cuda_runtime.h>
#include <cuda_bf16.h>
#include <math.h>
#include <stdint.h>

#define SS 1024
#define DD 128
#define NBH 24
#define NH 12

// scratch: scores (raw QK^T, lower-triangle tiles only)
__device__ float g_scores[(size_t)NBH * SS * SS];
// pre-split V planes (bf16 hi/lo), 16B-aligned for uint4 vector access
__device__ __align__(16) __nv_bfloat16 g_vh[(size_t)NBH * SS * DD];
__device__ __align__(16) __nv_bfloat16 g_vl[(size_t)NBH * SS * DD];
// split-K partials: unnormalized O and row sums, up to 4 splits per q-tile
__device__ float g_opart[4][(size_t)NBH * SS * DD];
__device__ float g_spart[4][NBH * SS];

// CTA -> (q-tile, split) map: q-tile qt has ceil((qt+1)/4) splits of <=4 chunks
__device__ const int8_t c_qt[40] = {0,1,2,3, 4,4, 5,5, 6,6, 7,7,
                                    8,8,8, 9,9,9, 10,10,10, 11,11,11,
                                    12,12,12,12, 13,13,13,13, 14,14,14,14, 15,15,15,15};
__device__ const int8_t c_sp[40] = {0,0,0,0, 0,1, 0,1, 0,1, 0,1,
                                    0,1,2, 0,1,2, 0,1,2, 0,1,2,
                                    0,1,2,3, 0,1,2,3, 0,1,2,3, 0,1,2,3};

__device__ __forceinline__ uint32_t smem_u32(const void* p) {
    uint32_t a;
    asm("{ .reg .u64 t; cvta.to.shared.u64 t, %1; cvt.u32.u64 %0, t; }"
        : "=r"(a) : "l"(p));
    return a;
}

#define LDMATRIX_X4(r0, r1, r2, r3, addr) \
    asm volatile("ldmatrix.sync.aligned.m8n8.x4.shared.b16 {%0,%1,%2,%3}, [%4];" \
                 : "=r"(r0), "=r"(r1), "=r"(r2), "=r"(r3) : "r"(addr))

#define LDMATRIX_X4_T(r0, r1, r2, r3, addr) \
    asm volatile("ldmatrix.sync.aligned.m8n8.x4.trans.shared.b16 {%0,%1,%2,%3}, [%4];" \
                 : "=r"(r0), "=r"(r1), "=r"(r2), "=r"(r3) : "r"(addr))

#define MMA_BF16(d, a, b) \
    asm volatile("mma.sync.aligned.m16n8k16.row.col.f32.bf16.bf16.f32 " \
                 "{%0,%1,%2,%3}, {%4,%5,%6,%7}, {%8,%9}, {%0,%1,%2,%3};" \
                 : "+f"((d)[0]), "+f"((d)[1]), "+f"((d)[2]), "+f"((d)[3]) \
                 : "r"((a)[0]), "r"((a)[1]), "r"((a)[2]), "r"((a)[3]), \
                   "r"((b)[0]), "r"((b)[1]))

// fast exp on the FMA pipe
__device__ __forceinline__ float fexp(float x) {
    float y = x * 1.4426950408889634f;
    y = fminf(fmaxf(y, -120.f), 120.f);
    float fy = floorf(y);
    float f = y - fy;
    float p = 1.5403530e-4f;
    p = fmaf(p, f, 1.3333558e-3f);
    p = fmaf(p, f, 9.6181291e-3f);
    p = fmaf(p, f, 5.5504109e-2f);
    p = fmaf(p, f, 2.4022651e-1f);
    p = fmaf(p, f, 6.9314718e-1f);
    p = fmaf(p, f, 1.0f);
    int e = (int)fy;
    return p * __int_as_float((e + 127) << 23);
}

__device__ __forceinline__ void split_store4(__nv_bfloat16* hi, __nv_bfloat16* lo, float4 v) {
    __nv_bfloat16 h0 = __float2bfloat16(v.x), h1 = __float2bfloat16(v.y);
    __nv_bfloat16 h2 = __float2bfloat16(v.z), h3 = __float2bfloat16(v.w);
    __nv_bfloat162 hp0(h0, h1), hp1(h2, h3);
    __nv_bfloat162 lp0 = __floats2bfloat162_rn(v.x - __bfloat162float(h0),
                                               v.y - __bfloat162float(h1));
    __nv_bfloat162 lp1 = __floats2bfloat162_rn(v.z - __bfloat162float(h2),
                                               v.w - __bfloat162float(h3));
    *(uint2*)hi = make_uint2(*(uint32_t*)&hp0, *(uint32_t*)&hp1);
    *(uint2*)lo = make_uint2(*(uint32_t*)&lp0, *(uint32_t*)&lp1);
}

// ---------------------------------------------------------------------------
// Kernel 0: pre-split V into bf16 hi/lo planes (done once, reused 8.5x)
// ---------------------------------------------------------------------------
__global__ __launch_bounds__(256) void vsplit_prep(const float* __restrict__ V)
{
    const size_t i = ((size_t)blockIdx.x * 256 + threadIdx.x) * 4;
    float4 v = *(const float4*)&V[i];
    split_store4(&g_vh[i], &g_vl[i], v);
}

// ---------------------------------------------------------------------------
// Kernel 1: scores = Q @ K^T via mma.sync bf16 split (3 terms)
// ---------------------------------------------------------------------------
#define LDE2 72
#define PLANE2 (128 * LDE2)

__global__ __launch_bounds__(256, 2) void qk_gemm_mma(
    const float* __restrict__ Q, const float* __restrict__ K)
{
    const int kt = blockIdx.x;
    const int qt = blockIdx.y;
    if (kt > qt) return;
    const int bh = blockIdx.z;

    extern __shared__ __align__(16) __nv_bfloat16 smem[];
    __nv_bfloat16* QH = smem;
    __nv_bfloat16* QL = smem + PLANE2;
    __nv_bfloat16* KH = smem + 2 * PLANE2;
    __nv_bfloat16* KL = smem + 3 * PLANE2;

    const int tid = threadIdx.x;
    const float* Qb = Q + ((size_t)bh * SS + (size_t)qt * 128) * DD;
    const float* Kb = K + ((size_t)bh * SS + (size_t)kt * 128) * DD;

    const int warp = tid >> 5, lane = tid & 31;
    const int m0 = (warp & 3) * 32;
    const int n0 = (warp >> 2) * 64;
    const int lrow = lane & 15;
    const int lgrp = lane >> 4;

    float acc[2][8][4] = {};

    for (int half = 0; half < 2; half++) {
        if (half) __syncthreads();
        for (int i = tid; i < 128 * 16; i += 256) {
            const int row = i >> 4, k = (i & 15) * 4;
            float4 v = *(const float4*)&Qb[(size_t)row * DD + half * 64 + k];
            split_store4(&QH[row * LDE2 + k], &QL[row * LDE2 + k], v);
            float4 u = *(const float4*)&Kb[(size_t)row * DD + half * 64 + k];
            split_store4(&KH[row * LDE2 + k], &KL[row * LDE2 + k], u);
        }
        __syncthreads();

        #pragma unroll
        for (int ks = 0; ks < 4; ks++) {
            const int kb = ks * 16;
            uint32_t ah[2][4], al[2][4];
            #pragma unroll
            for (int mi = 0; mi < 2; mi++) {
                uint32_t aH = smem_u32(&QH[(m0 + mi * 16 + lrow) * LDE2 + kb + lgrp * 8]);
                LDMATRIX_X4(ah[mi][0], ah[mi][1], ah[mi][2], ah[mi][3], aH);
                uint32_t aL = smem_u32(&QL[(m0 + mi * 16 + lrow) * LDE2 + kb + lgrp * 8]);
                LDMATRIX_X4(al[mi][0], al[mi][1], al[mi][2], al[mi][3], aL);
            }
            #pragma unroll
            for (int nfi = 0; nfi < 4; nfi++) {
                uint32_t bh4[4], bl4[4];
                uint32_t bHaddr = smem_u32(&KH[(n0 + nfi * 16 + lrow) * LDE2 + kb + lgrp * 8]);
                LDMATRIX_X4(bh4[0], bh4[1], bh4[2], bh4[3], bHaddr);
                uint32_t bLaddr = smem_u32(&KL[(n0 + nfi * 16 + lrow) * LDE2 + kb + lgrp * 8]);
                LDMATRIX_X4(bl4[0], bl4[1], bl4[2], bl4[3], bLaddr);

                uint32_t bh0[2] = {bh4[0], bh4[2]}, bh1[2] = {bh4[1], bh4[3]};
                uint32_t bl0[2] = {bl4[0], bl4[2]}, bl1[2] = {bl4[1], bl4[3]};

                #pragma unroll
                for (int mi = 0; mi < 2; mi++) {
                    MMA_BF16(acc[mi][2 * nfi],     ah[mi], bh0);
                    MMA_BF16(acc[mi][2 * nfi],     ah[mi], bl0);
                    MMA_BF16(acc[mi][2 * nfi],     al[mi], bh0);
                    MMA_BF16(acc[mi][2 * nfi + 1], ah[mi], bh1);
                    MMA_BF16(acc[mi][2 * nfi + 1], ah[mi], bl1);
                    MMA_BF16(acc[mi][2 * nfi + 1], al[mi], bh1);
                }
            }
        }
    }

    float* out = g_scores + (size_t)bh * SS * SS;
    const int g = lane >> 2, t2 = (lane & 3) * 2;
    #pragma unroll
    for (int mi = 0; mi < 2; mi++) {
        const int r1 = qt * 128 + m0 + mi * 16 + g;
        const int r2 = r1 + 8;
        #pragma unroll
        for (int nf = 0; nf < 8; nf++) {
            const int col = kt * 128 + n0 + nf * 8 + t2;
            *(float2*)&out[(size_t)r1 * SS + col] = make_float2(acc[mi][nf][0], acc[mi][nf][1]);
            *(float2*)&out[(size_t)r2 * SS + col] = make_float2(acc[mi][nf][2], acc[mi][nf][3]);
        }
    }
}

// ---------------------------------------------------------------------------
// Kernel 2 (fused, split-K balanced): conv (scalar fp32) + exp + P@V partial.
// V staged from pre-split hi/lo planes (correct full-row 16B copies).
// ---------------------------------------------------------------------------
#define PV_LDP 72    // P plane stride (bf16)
#define PV_LDV 136   // V plane stride (bf16)
#define S_LD 76      // score halo tile stride (float)

__global__ __launch_bounds__(256, 2) void conv_softmax_pv(const float* __restrict__ W)
{
    const int ent = blockIdx.x;       // 0..39
    const int bh = blockIdx.y;
    const int qt = c_qt[ent];
    const int sp = c_sp[ent];
    const int q0 = qt * 64;
    const int c0 = sp * 4;
    const int c1 = min(qt + 1, c0 + 4);

    const float* Sb = g_scores + (size_t)bh * SS * SS;
    const __nv_bfloat16* gvh = g_vh + (size_t)bh * SS * DD;
    const __nv_bfloat16* gvl = g_vl + (size_t)bh * SS * DD;

    extern __shared__ __align__(16) char dsm[];
    float* Ssh = (float*)dsm;                           // 69 x 76
    __nv_bfloat16* Ph = (__nv_bfloat16*)(Ssh + 69 * S_LD);
    __nv_bfloat16* Pl = Ph + 64 * PV_LDP;
    __nv_bfloat16* Vh = Pl + 64 * PV_LDP;               // 64 x 136
    __nv_bfloat16* Vl = Vh + 64 * PV_LDV;
    float* ws = (float*)(Vl + 64 * PV_LDV);             // 66

    const int tid = threadIdx.x;
    const int warp = tid >> 5, lane = tid & 31;
    const int m0 = (warp & 1) * 32;
    const int n0 = (warp >> 1) * 32;

    const int h = bh % NH;
    if (tid < 66) ws[tid] = W[h * 66 + tid];

    const int pr = tid >> 2;            // 0..63 (fixed q-row)
    const int pc = (tid & 3) * 16;      // 0..48 (16-key segment)
    const int pq = q0 + pr;
    float psum = 0.f;

    float acc[2][4][4] = {};

    const int lrow = lane & 15;
    const int lgrp = lane >> 4;
    const int bi = lane >> 3;
    const int brow = lane & 7;

    const float scale = 0.088388347648318447f;  // 1/sqrt(128)

    for (int ch = c0; ch < c1; ch++) {
        const int kc = ch * 64;
        if (ch > c0) __syncthreads();

        // stage scores halo tile (causal-masked at load)
        for (int i = tid; i < 69 * 74; i += 256) {
            const int rr = i / 74, cc = i % 74;
            const int q = q0 - 5 + rr;
            const int k = kc - 5 + cc;
            float v = 0.f;
            if (q >= 0 && k >= 0 && k <= q) v = Sb[(size_t)q * SS + k];
            Ssh[rr * S_LD + cc] = v;
        }
        // stage pre-split V chunk: uint4 = 8 bf16 per copy; 16 copies = full row
        for (int i = tid; i < 64 * 16; i += 256) {
            const int kr = i >> 4, c8 = (i & 15) * 8;
            *(uint4*)&Vh[kr * PV_LDV + c8] =
                *(const uint4*)&gvh[(size_t)(kc + kr) * DD + c8];
            *(uint4*)&Vl[kr * PV_LDV + c8] =
                *(const uint4*)&gvl[(size_t)(kc + kr) * DD + c8];
        }
        __syncthreads();

        // conv -> scale -> exp -> split-bf16 P (16 outputs per thread)
        {
            float out[16] = {};
            #pragma unroll
            for (int dq = 0; dq < 6; dq++) {
                float win[28];
                const float* srow = &Ssh[(pr + dq) * S_LD + pc];
                #pragma unroll
                for (int t4 = 0; t4 < 7; t4++)
                    *(float4*)&win[t4 * 4] = *(const float4*)&srow[t4 * 4];
                #pragma unroll
                for (int dk = 0; dk < 11; dk++) {
                    float w = ws[dq * 11 + dk];
                    #pragma unroll
                    for (int j = 0; j < 16; j++) out[j] += w * win[j + dk];
                }
            }
            #pragma unroll
            for (int j4 = 0; j4 < 4; j4++) {
                const int kbase = kc + pc + j4 * 4;
                float e0 = (kbase + 0 <= pq) ? fexp(out[j4*4+0] * scale) : 0.f;
                float e1 = (kbase + 1 <= pq) ? fexp(out[j4*4+1] * scale) : 0.f;
                float e2 = (kbase + 2 <= pq) ? fexp(out[j4*4+2] * scale) : 0.f;
                float e3 = (kbase + 3 <= pq) ? fexp(out[j4*4+3] * scale) : 0.f;
                psum += (e0 + e1) + (e2 + e3);
                split_store4(&Ph[pr * PV_LDP + pc + j4 * 4],
                             &Pl[pr * PV_LDP + pc + j4 * 4],
                             make_float4(e0, e1, e2, e3));
            }
        }
        __syncthreads();

        // 3-term HMMA: acc += Phi*Vhi + Phi*Vlo + Plo*Vhi
        #pragma unroll
        for (int ks = 0; ks < 4; ks++) {
            const int kb = ks * 16;
            uint32_t ah[2][4], al[2][4];
            #pragma unroll
            for (int mi = 0; mi < 2; mi++) {
                uint32_t aH = smem_u32(&Ph[(m0 + mi * 16 + lrow) * PV_LDP + kb + lgrp * 8]);
                LDMATRIX_X4(ah[mi][0], ah[mi][1], ah[mi][2], ah[mi][3], aH);
                uint32_t aL = smem_u32(&Pl[(m0 + mi * 16 + lrow) * PV_LDP + kb + lgrp * 8]);
                LDMATRIX_X4(al[mi][0], al[mi][1], al[mi][2], al[mi][3], aL);
            }
            #pragma unroll
            for (int ng = 0; ng < 2; ng++) {
                const int vrow = kb + (bi & 1) * 8 + brow;
                const int vcol = n0 + ng * 16 + (bi >> 1) * 8;
                uint32_t bh4[4], bl4[4];
                uint32_t bHaddr = smem_u32(&Vh[vrow * PV_LDV + vcol]);
                LDMATRIX_X4_T(bh4[0], bh4[1], bh4[2], bh4[3], bHaddr);
                uint32_t bLaddr = smem_u32(&Vl[vrow * PV_LDV + vcol]);
                LDMATRIX_X4_T(bl4[0], bl4[1], bl4[2], bl4[3], bLaddr);

                uint32_t bh0[2] = {bh4[0], bh4[1]}, bh1[2] = {bh4[2], bh4[3]};
                uint32_t bl0[2] = {bl4[0], bl4[1]}, bl1[2] = {bl4[2], bl4[3]};

                #pragma unroll
                for (int mi = 0; mi < 2; mi++) {
                    MMA_BF16(acc[mi][2 * ng],     ah[mi], bh0);
                    MMA_BF16(acc[mi][2 * ng],     ah[mi], bl0);
                    MMA_BF16(acc[mi][2 * ng],     al[mi], bh0);
                    MMA_BF16(acc[mi][2 * ng + 1], ah[mi], bh1);
                    MMA_BF16(acc[mi][2 * ng + 1], ah[mi], bl1);
                    MMA_BF16(acc[mi][2 * ng + 1], al[mi], bh1);
                }
            }
        }
    }

    // partial row sums (quad lanes share row pr)
    psum += __shfl_xor_sync(0xffffffffu, psum, 1);
    psum += __shfl_xor_sync(0xffffffffu, psum, 2);
    if ((tid & 3) == 0) g_spart[sp][bh * SS + q0 + pr] = psum;

    // write unnormalized partial O
    float* Op = g_opart[sp] + (size_t)bh * SS * DD;
    const int g = lane >> 2, t2 = (lane & 3) * 2;
    #pragma unroll
    for (int mi = 0; mi < 2; mi++) {
        const int lr1 = m0 + mi * 16 + g;
        const int lr2 = lr1 + 8;
        #pragma unroll
        for (int nf = 0; nf < 4; nf++) {
            const int col = n0 + nf * 8 + t2;
            *(float2*)&Op[(size_t)(q0 + lr1) * DD + col] =
                make_float2(acc[mi][nf][0], acc[mi][nf][1]);
            *(float2*)&Op[(size_t)(q0 + lr2) * DD + col] =
                make_float2(acc[mi][nf][2], acc[mi][nf][3]);
        }
    }
}

// ---------------------------------------------------------------------------
// Kernel 3: reduce partials and normalize.  O = (sum_s Op_s) / (sum_s rowSum_s)
// ---------------------------------------------------------------------------
__global__ __launch_bounds__(256) void reduce_out(float* __restrict__ O)
{
    const int row = blockIdx.x * 8 + (threadIdx.x >> 5);
    const int lane = threadIdx.x & 31;
    const int q = row & (SS - 1);
    const int ns = ((q >> 6) >> 2) + 1;

    float s = g_spart[0][row];
    if (ns > 1) s += g_spart[1][row];
    if (ns > 2) s += g_spart[2][row];
    if (ns > 3) s += g_spart[3][row];
    const float inv = 1.f / s;

    const size_t base = (size_t)row * DD + lane * 4;
    float4 a = *(const float4*)&g_opart[0][base];
    if (ns > 1) {
        float4 v = *(const float4*)&g_opart[1][base];
        a.x += v.x; a.y += v.y; a.z += v.z; a.w += v.w;
    }
    if (ns > 2) {
        float4 v = *(const float4*)&g_opart[2][base];
        a.x += v.x; a.y += v.y; a.z += v.z; a.w += v.w;
    }
    if (ns > 3) {
        float4 v = *(const float4*)&g_opart[3][base];
        a.x += v.x; a.y += v.y; a.z += v.z; a.w += v.w;
    }
    *(float4*)&O[base] = make_float4(a.x * inv, a.y * inv, a.z * inv, a.w * inv);
}

// ---------------------------------------------------------------------------
extern "C" void kernel_launch(void* const* d_in, const int* in_sizes, int n_in,
                              void* d_out, int out_size)
{
    const float* Q = (const float*)d_in[0];
    const float* K = (const float*)d_in[1];
    const float* V = (const float*)d_in[2];
    const float* W = (const float*)d_in[3];
    float* O = (float*)d_out;

    const int QK_SMEM = 4 * PLANE2 * (int)sizeof(__nv_bfloat16);  // 73728 B
    cudaFuncSetAttribute(qk_gemm_mma, cudaFuncAttributeMaxDynamicSharedMemorySize, QK_SMEM);

    const int PV_SMEM = 69 * S_LD * (int)sizeof(float)
                      + (2 * 64 * PV_LDP + 2 * 64 * PV_LDV) * (int)sizeof(__nv_bfloat16)
                      + 66 * (int)sizeof(float);                  // ~74.4 KB
    cudaFuncSetAttribute(conv_softmax_pv, cudaFuncAttributeMaxDynamicSharedMemorySize, PV_SMEM);

    vsplit_prep<<<(NBH * SS * DD) / (256 * 4), 256>>>(V);

    dim3 g1(8, 8, NBH);
    qk_gemm_mma<<<g1, 256, QK_SMEM>>>(Q, K);

    dim3 g2(40, NBH);
    conv_softmax_pv<<<g2, 256, PV_SMEM>>>(W);

    reduce_out<<<NBH * SS / 8, 256>>>(O);
}

// round 16
// speedup vs baseline: 1.0983x; 1.0545x over previous
#include <cuda_runtime.h>
#include <cuda_bf16.h>
#include <math.h>
#include <stdint.h>

#define SS 1024
#define DD 128
#define NBH 24
#define NH 12

// scratch: scores (raw QK^T, lower-triangle tiles only)
__device__ float g_scores[(size_t)NBH * SS * SS];
// split-K partials: unnormalized O and row sums, up to 4 splits per q-tile
__device__ float g_opart[4][(size_t)NBH * SS * DD];
__device__ float g_spart[4][NBH * SS];

// CTA -> (q-tile, split) map: q-tile qt has ceil((qt+1)/4) splits of <=4 chunks
__device__ const int8_t c_qt[40] = {0,1,2,3, 4,4, 5,5, 6,6, 7,7,
                                    8,8,8, 9,9,9, 10,10,10, 11,11,11,
                                    12,12,12,12, 13,13,13,13, 14,14,14,14, 15,15,15,15};
__device__ const int8_t c_sp[40] = {0,0,0,0, 0,1, 0,1, 0,1, 0,1,
                                    0,1,2, 0,1,2, 0,1,2, 0,1,2,
                                    0,1,2,3, 0,1,2,3, 0,1,2,3, 0,1,2,3};

__device__ __forceinline__ uint32_t smem_u32(const void* p) {
    uint32_t a;
    asm("{ .reg .u64 t; cvta.to.shared.u64 t, %1; cvt.u32.u64 %0, t; }"
        : "=r"(a) : "l"(p));
    return a;
}

#define LDMATRIX_X4(r0, r1, r2, r3, addr) \
    asm volatile("ldmatrix.sync.aligned.m8n8.x4.shared.b16 {%0,%1,%2,%3}, [%4];" \
                 : "=r"(r0), "=r"(r1), "=r"(r2), "=r"(r3) : "r"(addr))

#define LDMATRIX_X4_T(r0, r1, r2, r3, addr) \
    asm volatile("ldmatrix.sync.aligned.m8n8.x4.trans.shared.b16 {%0,%1,%2,%3}, [%4];" \
                 : "=r"(r0), "=r"(r1), "=r"(r2), "=r"(r3) : "r"(addr))

#define MMA_BF16(d, a, b0, b1) \
    asm volatile("mma.sync.aligned.m16n8k16.row.col.f32.bf16.bf16.f32 " \
                 "{%0,%1,%2,%3}, {%4,%5,%6,%7}, {%8,%9}, {%0,%1,%2,%3};" \
                 : "+f"((d)[0]), "+f"((d)[1]), "+f"((d)[2]), "+f"((d)[3]) \
                 : "r"((a)[0]), "r"((a)[1]), "r"((a)[2]), "r"((a)[3]), \
                   "r"(b0), "r"(b1))

// fast exp on the FMA pipe
__device__ __forceinline__ float fexp(float x) {
    float y = x * 1.4426950408889634f;
    y = fminf(fmaxf(y, -120.f), 120.f);
    float fy = floorf(y);
    float f = y - fy;
    float p = 1.5403530e-4f;
    p = fmaf(p, f, 1.3333558e-3f);
    p = fmaf(p, f, 9.6181291e-3f);
    p = fmaf(p, f, 5.5504109e-2f);
    p = fmaf(p, f, 2.4022651e-1f);
    p = fmaf(p, f, 6.9314718e-1f);
    p = fmaf(p, f, 1.0f);
    int e = (int)fy;
    return p * __int_as_float((e + 127) << 23);
}

__device__ __forceinline__ void split_store4(__nv_bfloat16* hi, __nv_bfloat16* lo, float4 v) {
    __nv_bfloat16 h0 = __float2bfloat16(v.x), h1 = __float2bfloat16(v.y);
    __nv_bfloat16 h2 = __float2bfloat16(v.z), h3 = __float2bfloat16(v.w);
    __nv_bfloat162 hp0(h0, h1), hp1(h2, h3);
    __nv_bfloat162 lp0 = __floats2bfloat162_rn(v.x - __bfloat162float(h0),
                                               v.y - __bfloat162float(h1));
    __nv_bfloat162 lp1 = __floats2bfloat162_rn(v.z - __bfloat162float(h2),
                                               v.w - __bfloat162float(h3));
    *(uint2*)hi = make_uint2(*(uint32_t*)&hp0, *(uint32_t*)&hp1);
    *(uint2*)lo = make_uint2(*(uint32_t*)&lp0, *(uint32_t*)&lp1);
}

// ---------------------------------------------------------------------------
// Kernel 1: scores = Q @ K^T via mma.sync bf16 split (3 terms), term-major
// MMA scheduling (same-acc reuse distance 8) to break dependency stalls.
// ---------------------------------------------------------------------------
#define LDE2 72
#define PLANE2 (128 * LDE2)

__global__ __launch_bounds__(256, 2) void qk_gemm_mma(
    const float* __restrict__ Q, const float* __restrict__ K)
{
    const int kt = blockIdx.x;
    const int qt = blockIdx.y;
    if (kt > qt) return;
    const int bh = blockIdx.z;

    extern __shared__ __align__(16) __nv_bfloat16 smem[];
    __nv_bfloat16* QH = smem;
    __nv_bfloat16* QL = smem + PLANE2;
    __nv_bfloat16* KH = smem + 2 * PLANE2;
    __nv_bfloat16* KL = smem + 3 * PLANE2;

    const int tid = threadIdx.x;
    const float* Qb = Q + ((size_t)bh * SS + (size_t)qt * 128) * DD;
    const float* Kb = K + ((size_t)bh * SS + (size_t)kt * 128) * DD;

    const int warp = tid >> 5, lane = tid & 31;
    const int m0 = (warp & 3) * 32;
    const int n0 = (warp >> 2) * 64;
    const int lrow = lane & 15;
    const int lgrp = lane >> 4;

    float acc[2][8][4] = {};

    for (int half = 0; half < 2; half++) {
        if (half) __syncthreads();
        for (int i = tid; i < 128 * 16; i += 256) {
            const int row = i >> 4, k = (i & 15) * 4;
            float4 v = *(const float4*)&Qb[(size_t)row * DD + half * 64 + k];
            split_store4(&QH[row * LDE2 + k], &QL[row * LDE2 + k], v);
            float4 u = *(const float4*)&Kb[(size_t)row * DD + half * 64 + k];
            split_store4(&KH[row * LDE2 + k], &KL[row * LDE2 + k], u);
        }
        __syncthreads();

        #pragma unroll
        for (int ks = 0; ks < 4; ks++) {
            const int kb = ks * 16;
            uint32_t ah[2][4], al[2][4];
            #pragma unroll
            for (int mi = 0; mi < 2; mi++) {
                uint32_t aH = smem_u32(&QH[(m0 + mi * 16 + lrow) * LDE2 + kb + lgrp * 8]);
                LDMATRIX_X4(ah[mi][0], ah[mi][1], ah[mi][2], ah[mi][3], aH);
                uint32_t aL = smem_u32(&QL[(m0 + mi * 16 + lrow) * LDE2 + kb + lgrp * 8]);
                LDMATRIX_X4(al[mi][0], al[mi][1], al[mi][2], al[mi][3], aL);
            }
            #pragma unroll
            for (int nfp = 0; nfp < 2; nfp++) {
                // load B frags for the pair of 16-wide n-tiles
                uint32_t bh4[2][4], bl4[2][4];
                #pragma unroll
                for (int j = 0; j < 2; j++) {
                    const int nn = n0 + (nfp * 2 + j) * 16;
                    uint32_t bHaddr = smem_u32(&KH[(nn + lrow) * LDE2 + kb + lgrp * 8]);
                    LDMATRIX_X4(bh4[j][0], bh4[j][1], bh4[j][2], bh4[j][3], bHaddr);
                    uint32_t bLaddr = smem_u32(&KL[(nn + lrow) * LDE2 + kb + lgrp * 8]);
                    LDMATRIX_X4(bl4[j][0], bl4[j][1], bl4[j][2], bl4[j][3], bLaddr);
                }
                // frag f = 2*j + fr: hi pair {bh4[j][fr], bh4[j][fr+2]}
                // term-major: each of the 8 accs touched once per term
                #pragma unroll
                for (int f = 0; f < 4; f++) {   // term hh
                    const int j = f >> 1, fr = f & 1;
                    #pragma unroll
                    for (int mi = 0; mi < 2; mi++)
                        MMA_BF16(acc[mi][4 * nfp + f], ah[mi], bh4[j][fr], bh4[j][fr + 2]);
                }
                #pragma unroll
                for (int f = 0; f < 4; f++) {   // term hl
                    const int j = f >> 1, fr = f & 1;
                    #pragma unroll
                    for (int mi = 0; mi < 2; mi++)
                        MMA_BF16(acc[mi][4 * nfp + f], ah[mi], bl4[j][fr], bl4[j][fr + 2]);
                }
                #pragma unroll
                for (int f = 0; f < 4; f++) {   // term lh
                    const int j = f >> 1, fr = f & 1;
                    #pragma unroll
                    for (int mi = 0; mi < 2; mi++)
                        MMA_BF16(acc[mi][4 * nfp + f], al[mi], bh4[j][fr], bh4[j][fr + 2]);
                }
            }
        }
    }

    float* out = g_scores + (size_t)bh * SS * SS;
    const int g = lane >> 2, t2 = (lane & 3) * 2;
    #pragma unroll
    for (int mi = 0; mi < 2; mi++) {
        const int r1 = qt * 128 + m0 + mi * 16 + g;
        const int r2 = r1 + 8;
        #pragma unroll
        for (int nf = 0; nf < 8; nf++) {
            const int col = kt * 128 + n0 + nf * 8 + t2;
            *(float2*)&out[(size_t)r1 * SS + col] = make_float2(acc[mi][nf][0], acc[mi][nf][1]);
            *(float2*)&out[(size_t)r2 * SS + col] = make_float2(acc[mi][nf][2], acc[mi][nf][3]);
        }
    }
}

// ---------------------------------------------------------------------------
// Kernel 2 (fused, split-K balanced): conv (scalar) + exp + P@V partial,
// term-major MMA scheduling. V split in-kernel (R10 form).
// ---------------------------------------------------------------------------
#define PV_LDP 72    // P plane stride (bf16)
#define PV_LDV 136   // V plane stride (bf16)
#define S_LD 76      // score halo tile stride (float)

__global__ __launch_bounds__(256, 2) void conv_softmax_pv(
    const float* __restrict__ V, const float* __restrict__ W)
{
    const int ent = blockIdx.x;       // 0..39
    const int bh = blockIdx.y;
    const int qt = c_qt[ent];
    const int sp = c_sp[ent];
    const int q0 = qt * 64;
    const int c0 = sp * 4;
    const int c1 = min(qt + 1, c0 + 4);

    const float* Sb = g_scores + (size_t)bh * SS * SS;
    const float* Vb = V + (size_t)bh * SS * DD;

    extern __shared__ __align__(16) char dsm[];
    float* Ssh = (float*)dsm;                           // 69 x 76
    __nv_bfloat16* Ph = (__nv_bfloat16*)(Ssh + 69 * S_LD);
    __nv_bfloat16* Pl = Ph + 64 * PV_LDP;
    __nv_bfloat16* Vh = Pl + 64 * PV_LDP;               // 64 x 136
    __nv_bfloat16* Vl = Vh + 64 * PV_LDV;
    float* ws = (float*)(Vl + 64 * PV_LDV);             // 66

    const int tid = threadIdx.x;
    const int warp = tid >> 5, lane = tid & 31;
    const int m0 = (warp & 1) * 32;
    const int n0 = (warp >> 1) * 32;

    const int h = bh % NH;
    if (tid < 66) ws[tid] = W[h * 66 + tid];

    const int pr = tid >> 2;            // 0..63 (fixed q-row)
    const int pc = (tid & 3) * 16;      // 0..48 (16-key segment)
    const int pq = q0 + pr;
    float psum = 0.f;

    float acc[2][4][4] = {};

    const int lrow = lane & 15;
    const int lgrp = lane >> 4;
    const int bi = lane >> 3;
    const int brow = lane & 7;

    const float scale = 0.088388347648318447f;  // 1/sqrt(128)

    for (int ch = c0; ch < c1; ch++) {
        const int kc = ch * 64;
        if (ch > c0) __syncthreads();

        // stage scores halo tile (causal-masked at load)
        for (int i = tid; i < 69 * 74; i += 256) {
            const int rr = i / 74, cc = i % 74;
            const int q = q0 - 5 + rr;
            const int k = kc - 5 + cc;
            float v = 0.f;
            if (q >= 0 && k >= 0 && k <= q) v = Sb[(size_t)q * SS + k];
            Ssh[rr * S_LD + cc] = v;
        }
        // stage V chunk 64 x 128 -> hi/lo (in-kernel split, R10 form)
        for (int i = tid; i < 64 * 32; i += 256) {
            const int kr = i >> 5, c = (i & 31) * 4;
            float4 v = *(const float4*)&Vb[(size_t)(kc + kr) * DD + c];
            split_store4(&Vh[kr * PV_LDV + c], &Vl[kr * PV_LDV + c], v);
        }
        __syncthreads();

        // conv -> scale -> exp -> split-bf16 P (16 outputs per thread)
        {
            float out[16] = {};
            #pragma unroll
            for (int dq = 0; dq < 6; dq++) {
                float win[28];
                const float* srow = &Ssh[(pr + dq) * S_LD + pc];
                #pragma unroll
                for (int t4 = 0; t4 < 7; t4++)
                    *(float4*)&win[t4 * 4] = *(const float4*)&srow[t4 * 4];
                #pragma unroll
                for (int dk = 0; dk < 11; dk++) {
                    float w = ws[dq * 11 + dk];
                    #pragma unroll
                    for (int j = 0; j < 16; j++) out[j] += w * win[j + dk];
                }
            }
            #pragma unroll
            for (int j4 = 0; j4 < 4; j4++) {
                const int kbase = kc + pc + j4 * 4;
                float e0 = (kbase + 0 <= pq) ? fexp(out[j4*4+0] * scale) : 0.f;
                float e1 = (kbase + 1 <= pq) ? fexp(out[j4*4+1] * scale) : 0.f;
                float e2 = (kbase + 2 <= pq) ? fexp(out[j4*4+2] * scale) : 0.f;
                float e3 = (kbase + 3 <= pq) ? fexp(out[j4*4+3] * scale) : 0.f;
                psum += (e0 + e1) + (e2 + e3);
                split_store4(&Ph[pr * PV_LDP + pc + j4 * 4],
                             &Pl[pr * PV_LDP + pc + j4 * 4],
                             make_float4(e0, e1, e2, e3));
            }
        }
        __syncthreads();

        // 3-term HMMA, term-major: each of the 8 accs touched once per term
        #pragma unroll
        for (int ks = 0; ks < 4; ks++) {
            const int kb = ks * 16;
            uint32_t ah[2][4], al[2][4];
            #pragma unroll
            for (int mi = 0; mi < 2; mi++) {
                uint32_t aH = smem_u32(&Ph[(m0 + mi * 16 + lrow) * PV_LDP + kb + lgrp * 8]);
                LDMATRIX_X4(ah[mi][0], ah[mi][1], ah[mi][2], ah[mi][3], aH);
                uint32_t aL = smem_u32(&Pl[(m0 + mi * 16 + lrow) * PV_LDP + kb + lgrp * 8]);
                LDMATRIX_X4(al[mi][0], al[mi][1], al[mi][2], al[mi][3], aL);
            }
            // load V frags for both n-groups
            uint32_t vh4[2][4], vl4[2][4];
            #pragma unroll
            for (int ng = 0; ng < 2; ng++) {
                const int vrow = kb + (bi & 1) * 8 + brow;
                const int vcol = n0 + ng * 16 + (bi >> 1) * 8;
                uint32_t bHaddr = smem_u32(&Vh[vrow * PV_LDV + vcol]);
                LDMATRIX_X4_T(vh4[ng][0], vh4[ng][1], vh4[ng][2], vh4[ng][3], bHaddr);
                uint32_t bLaddr = smem_u32(&Vl[vrow * PV_LDV + vcol]);
                LDMATRIX_X4_T(vl4[ng][0], vl4[ng][1], vl4[ng][2], vl4[ng][3], bLaddr);
            }
            // frag f = 2*ng + fr: pair {v4[ng][2fr], v4[ng][2fr+1]}
            #pragma unroll
            for (int f = 0; f < 4; f++) {   // term PhiVhi
                const int ng = f >> 1, fr = f & 1;
                #pragma unroll
                for (int mi = 0; mi < 2; mi++)
                    MMA_BF16(acc[mi][f], ah[mi], vh4[ng][2 * fr], vh4[ng][2 * fr + 1]);
            }
            #pragma unroll
            for (int f = 0; f < 4; f++) {   // term PhiVlo
                const int ng = f >> 1, fr = f & 1;
                #pragma unroll
                for (int mi = 0; mi < 2; mi++)
                    MMA_BF16(acc[mi][f], ah[mi], vl4[ng][2 * fr], vl4[ng][2 * fr + 1]);
            }
            #pragma unroll
            for (int f = 0; f < 4; f++) {   // term PloVhi
                const int ng = f >> 1, fr = f & 1;
                #pragma unroll
                for (int mi = 0; mi < 2; mi++)
                    MMA_BF16(acc[mi][f], al[mi], vh4[ng][2 * fr], vh4[ng][2 * fr + 1]);
            }
        }
    }

    // partial row sums (quad lanes share row pr)
    psum += __shfl_xor_sync(0xffffffffu, psum, 1);
    psum += __shfl_xor_sync(0xffffffffu, psum, 2);
    if ((tid & 3) == 0) g_spart[sp][bh * SS + q0 + pr] = psum;

    // write unnormalized partial O
    float* Op = g_opart[sp] + (size_t)bh * SS * DD;
    const int g = lane >> 2, t2 = (lane & 3) * 2;
    #pragma unroll
    for (int mi = 0; mi < 2; mi++) {
        const int lr1 = m0 + mi * 16 + g;
        const int lr2 = lr1 + 8;
        #pragma unroll
        for (int nf = 0; nf < 4; nf++) {
            const int col = n0 + nf * 8 + t2;
            *(float2*)&Op[(size_t)(q0 + lr1) * DD + col] =
                make_float2(acc[mi][nf][0], acc[mi][nf][1]);
            *(float2*)&Op[(size_t)(q0 + lr2) * DD + col] =
                make_float2(acc[mi][nf][2], acc[mi][nf][3]);
        }
    }
}

// ---------------------------------------------------------------------------
// Kernel 3: reduce partials and normalize.  O = (sum_s Op_s) / (sum_s rowSum_s)
// ---------------------------------------------------------------------------
__global__ __launch_bounds__(256) void reduce_out(float* __restrict__ O)
{
    const int row = blockIdx.x * 8 + (threadIdx.x >> 5);
    const int lane = threadIdx.x & 31;
    const int q = row & (SS - 1);
    const int ns = ((q >> 6) >> 2) + 1;

    float s = g_spart[0][row];
    if (ns > 1) s += g_spart[1][row];
    if (ns > 2) s += g_spart[2][row];
    if (ns > 3) s += g_spart[3][row];
    const float inv = 1.f / s;

    const size_t base = (size_t)row * DD + lane * 4;
    float4 a = *(const float4*)&g_opart[0][base];
    if (ns > 1) {
        float4 v = *(const float4*)&g_opart[1][base];
        a.x += v.x; a.y += v.y; a.z += v.z; a.w += v.w;
    }
    if (ns > 2) {
        float4 v = *(const float4*)&g_opart[2][base];
        a.x += v.x; a.y += v.y; a.z += v.z; a.w += v.w;
    }
    if (ns > 3) {
        float4 v = *(const float4*)&g_opart[3][base];
        a.x += v.x; a.y += v.y; a.z += v.z; a.w += v.w;
    }
    *(float4*)&O[base] = make_float4(a.x * inv, a.y * inv, a.z * inv, a.w * inv);
}

// ---------------------------------------------------------------------------
extern "C" void kernel_launch(void* const* d_in, const int* in_sizes, int n_in,
                              void* d_out, int out_size)
{
    const float* Q = (const float*)d_in[0];
    const float* K = (const float*)d_in[1];
    const float* V = (const float*)d_in[2];
    const float* W = (const float*)d_in[3];
    float* O = (float*)d_out;

    const int QK_SMEM = 4 * PLANE2 * (int)sizeof(__nv_bfloat16);  // 73728 B
    cudaFuncSetAttribute(qk_gemm_mma, cudaFuncAttributeMaxDynamicSharedMemorySize, QK_SMEM);

    const int PV_SMEM = 69 * S_LD * (int)sizeof(float)
                      + (2 * 64 * PV_LDP + 2 * 64 * PV_LDV) * (int)sizeof(__nv_bfloat16)
                      + 66 * (int)sizeof(float);                  // ~74.4 KB
    cudaFuncSetAttribute(conv_softmax_pv, cudaFuncAttributeMaxDynamicSharedMemorySize, PV_SMEM);

    dim3 g1(8, 8, NBH);
    qk_gemm_mma<<<g1, 256, QK_SMEM>>>(Q, K);

    dim3 g2(40, NBH);
    conv_softmax_pv<<<g2, 256, PV_SMEM>>>(V, W);

    reduce_out<<<NBH * SS / 8, 256>>>(O);
}

// round 17
// speedup vs baseline: 1.1531x; 1.0499x over previous
#include <cuda_runtime.h>
#include <cuda_bf16.h>
#include <math.h>
#include <stdint.h>

#define SS 1024
#define DD 128
#define NBH 24
#define NH 12

// scratch: scores (raw QK^T, lower-triangle tiles only)
__device__ float g_scores[(size_t)NBH * SS * SS];
// split-K partials: unnormalized O and row sums, up to 4 splits per q-tile
__device__ float g_opart[4][(size_t)NBH * SS * DD];
__device__ float g_spart[4][NBH * SS];

// CTA -> (q-tile, split) map: q-tile qt has ceil((qt+1)/4) splits of <=4 chunks
__device__ const int8_t c_qt[40] = {0,1,2,3, 4,4, 5,5, 6,6, 7,7,
                                    8,8,8, 9,9,9, 10,10,10, 11,11,11,
                                    12,12,12,12, 13,13,13,13, 14,14,14,14, 15,15,15,15};
__device__ const int8_t c_sp[40] = {0,0,0,0, 0,1, 0,1, 0,1, 0,1,
                                    0,1,2, 0,1,2, 0,1,2, 0,1,2,
                                    0,1,2,3, 0,1,2,3, 0,1,2,3, 0,1,2,3};

__device__ __forceinline__ uint32_t smem_u32(const void* p) {
    uint32_t a;
    asm("{ .reg .u64 t; cvta.to.shared.u64 t, %1; cvt.u32.u64 %0, t; }"
        : "=r"(a) : "l"(p));
    return a;
}

#define LDMATRIX_X4(r0, r1, r2, r3, addr) \
    asm volatile("ldmatrix.sync.aligned.m8n8.x4.shared.b16 {%0,%1,%2,%3}, [%4];" \
                 : "=r"(r0), "=r"(r1), "=r"(r2), "=r"(r3) : "r"(addr))

#define LDMATRIX_X4_T(r0, r1, r2, r3, addr) \
    asm volatile("ldmatrix.sync.aligned.m8n8.x4.trans.shared.b16 {%0,%1,%2,%3}, [%4];" \
                 : "=r"(r0), "=r"(r1), "=r"(r2), "=r"(r3) : "r"(addr))

#define MMA_BF16(d, a, b0, b1) \
    asm volatile("mma.sync.aligned.m16n8k16.row.col.f32.bf16.bf16.f32 " \
                 "{%0,%1,%2,%3}, {%4,%5,%6,%7}, {%8,%9}, {%0,%1,%2,%3};" \
                 : "+f"((d)[0]), "+f"((d)[1]), "+f"((d)[2]), "+f"((d)[3]) \
                 : "r"((a)[0]), "r"((a)[1]), "r"((a)[2]), "r"((a)[3]), \
                   "r"(b0), "r"(b1))

__device__ __forceinline__ void split_store4(__nv_bfloat16* hi, __nv_bfloat16* lo, float4 v) {
    __nv_bfloat16 h0 = __float2bfloat16(v.x), h1 = __float2bfloat16(v.y);
    __nv_bfloat16 h2 = __float2bfloat16(v.z), h3 = __float2bfloat16(v.w);
    __nv_bfloat162 hp0(h0, h1), hp1(h2, h3);
    __nv_bfloat162 lp0 = __floats2bfloat162_rn(v.x - __bfloat162float(h0),
                                               v.y - __bfloat162float(h1));
    __nv_bfloat162 lp1 = __floats2bfloat162_rn(v.z - __bfloat162float(h2),
                                               v.w - __bfloat162float(h3));
    *(uint2*)hi = make_uint2(*(uint32_t*)&hp0, *(uint32_t*)&hp1);
    *(uint2*)lo = make_uint2(*(uint32_t*)&lp0, *(uint32_t*)&lp1);
}

// ---------------------------------------------------------------------------
// Kernel 1: scores = Q @ K^T via mma.sync bf16 split (3 terms)
// ---------------------------------------------------------------------------
#define LDE2 72
#define PLANE2 (128 * LDE2)

__global__ __launch_bounds__(256, 2) void qk_gemm_mma(
    const float* __restrict__ Q, const float* __restrict__ K)
{
    const int kt = blockIdx.x;
    const int qt = blockIdx.y;
    if (kt > qt) return;
    const int bh = blockIdx.z;

    extern __shared__ __align__(16) __nv_bfloat16 smem[];
    __nv_bfloat16* QH = smem;
    __nv_bfloat16* QL = smem + PLANE2;
    __nv_bfloat16* KH = smem + 2 * PLANE2;
    __nv_bfloat16* KL = smem + 3 * PLANE2;

    const int tid = threadIdx.x;
    const float* Qb = Q + ((size_t)bh * SS + (size_t)qt * 128) * DD;
    const float* Kb = K + ((size_t)bh * SS + (size_t)kt * 128) * DD;

    const int warp = tid >> 5, lane = tid & 31;
    const int m0 = (warp & 3) * 32;
    const int n0 = (warp >> 2) * 64;
    const int lrow = lane & 15;
    const int lgrp = lane >> 4;

    float acc[2][8][4] = {};

    for (int half = 0; half < 2; half++) {
        if (half) __syncthreads();
        for (int i = tid; i < 128 * 16; i += 256) {
            const int row = i >> 4, k = (i & 15) * 4;
            float4 v = *(const float4*)&Qb[(size_t)row * DD + half * 64 + k];
            split_store4(&QH[row * LDE2 + k], &QL[row * LDE2 + k], v);
            float4 u = *(const float4*)&Kb[(size_t)row * DD + half * 64 + k];
            split_store4(&KH[row * LDE2 + k], &KL[row * LDE2 + k], u);
        }
        __syncthreads();

        #pragma unroll
        for (int ks = 0; ks < 4; ks++) {
            const int kb = ks * 16;
            uint32_t ah[2][4], al[2][4];
            #pragma unroll
            for (int mi = 0; mi < 2; mi++) {
                uint32_t aH = smem_u32(&QH[(m0 + mi * 16 + lrow) * LDE2 + kb + lgrp * 8]);
                LDMATRIX_X4(ah[mi][0], ah[mi][1], ah[mi][2], ah[mi][3], aH);
                uint32_t aL = smem_u32(&QL[(m0 + mi * 16 + lrow) * LDE2 + kb + lgrp * 8]);
                LDMATRIX_X4(al[mi][0], al[mi][1], al[mi][2], al[mi][3], aL);
            }
            #pragma unroll
            for (int nfi = 0; nfi < 4; nfi++) {
                uint32_t bh4[4], bl4[4];
                uint32_t bHaddr = smem_u32(&KH[(n0 + nfi * 16 + lrow) * LDE2 + kb + lgrp * 8]);
                LDMATRIX_X4(bh4[0], bh4[1], bh4[2], bh4[3], bHaddr);
                uint32_t bLaddr = smem_u32(&KL[(n0 + nfi * 16 + lrow) * LDE2 + kb + lgrp * 8]);
                LDMATRIX_X4(bl4[0], bl4[1], bl4[2], bl4[3], bLaddr);

                #pragma unroll
                for (int mi = 0; mi < 2; mi++) {
                    MMA_BF16(acc[mi][2 * nfi],     ah[mi], bh4[0], bh4[2]);
                    MMA_BF16(acc[mi][2 * nfi],     ah[mi], bl4[0], bl4[2]);
                    MMA_BF16(acc[mi][2 * nfi],     al[mi], bh4[0], bh4[2]);
                    MMA_BF16(acc[mi][2 * nfi + 1], ah[mi], bh4[1], bh4[3]);
                    MMA_BF16(acc[mi][2 * nfi + 1], ah[mi], bl4[1], bl4[3]);
                    MMA_BF16(acc[mi][2 * nfi + 1], al[mi], bh4[1], bh4[3]);
                }
            }
        }
    }

    float* out = g_scores + (size_t)bh * SS * SS;
    const int g = lane >> 2, t2 = (lane & 3) * 2;
    #pragma unroll
    for (int mi = 0; mi < 2; mi++) {
        const int r1 = qt * 128 + m0 + mi * 16 + g;
        const int r2 = r1 + 8;
        #pragma unroll
        for (int nf = 0; nf < 8; nf++) {
            const int col = kt * 128 + n0 + nf * 8 + t2;
            *(float2*)&out[(size_t)r1 * SS + col] = make_float2(acc[mi][nf][0], acc[mi][nf][1]);
            *(float2*)&out[(size_t)r2 * SS + col] = make_float2(acc[mi][nf][2], acc[mi][nf][3]);
        }
    }
}

// ---------------------------------------------------------------------------
// Kernel 2 (fused, split-K balanced): conv + exp + P@V partial.
// FMA-pipe relief: exp on MUFU (__expf), scale folded into weights, unmasked
// fast-path staging for interior chunks.
// ---------------------------------------------------------------------------
#define PV_LDP 72    // P plane stride (bf16)
#define PV_LDV 136   // V plane stride (bf16)
#define S_LD 76      // score halo tile stride (float)

__global__ __launch_bounds__(256, 2) void conv_softmax_pv(
    const float* __restrict__ V, const float* __restrict__ W)
{
    const int ent = blockIdx.x;       // 0..39
    const int bh = blockIdx.y;
    const int qt = c_qt[ent];
    const int sp = c_sp[ent];
    const int q0 = qt * 64;
    const int c0 = sp * 4;
    const int c1 = min(qt + 1, c0 + 4);

    const float* Sb = g_scores + (size_t)bh * SS * SS;
    const float* Vb = V + (size_t)bh * SS * DD;

    extern __shared__ __align__(16) char dsm[];
    float* Ssh = (float*)dsm;                           // 69 x 76
    __nv_bfloat16* Ph = (__nv_bfloat16*)(Ssh + 69 * S_LD);
    __nv_bfloat16* Pl = Ph + 64 * PV_LDP;
    __nv_bfloat16* Vh = Pl + 64 * PV_LDP;               // 64 x 136
    __nv_bfloat16* Vl = Vh + 64 * PV_LDV;
    float* ws = (float*)(Vl + 64 * PV_LDV);             // 66 (pre-scaled)

    const int tid = threadIdx.x;
    const int warp = tid >> 5, lane = tid & 31;
    const int m0 = (warp & 1) * 32;
    const int n0 = (warp >> 1) * 32;

    const int h = bh % NH;
    const float scale = 0.088388347648318447f;  // 1/sqrt(128)
    if (tid < 66) ws[tid] = W[h * 66 + tid] * scale;

    const int pr = tid >> 2;            // 0..63 (fixed q-row)
    const int pc = (tid & 3) * 16;      // 0..48 (16-key segment)
    const int pq = q0 + pr;
    float psum = 0.f;

    float acc[2][4][4] = {};

    const int lrow = lane & 15;
    const int lgrp = lane >> 4;
    const int bi = lane >> 3;
    const int brow = lane & 7;

    for (int ch = c0; ch < c1; ch++) {
        const int kc = ch * 64;
        if (ch > c0) __syncthreads();

        // stage scores halo tile. Interior chunks (1 <= ch <= qt-2) are
        // provably in-bounds and fully causal -> unmasked loads.
        if (ch >= 1 && ch + 2 <= qt) {
            const float* Sh0 = &Sb[(size_t)(q0 - 5) * SS + (kc - 5)];
            for (int i = tid; i < 69 * 74; i += 256) {
                const int rr = i / 74, cc = i % 74;
                Ssh[rr * S_LD + cc] = Sh0[(size_t)rr * SS + cc];
            }
        } else {
            for (int i = tid; i < 69 * 74; i += 256) {
                const int rr = i / 74, cc = i % 74;
                const int q = q0 - 5 + rr;
                const int k = kc - 5 + cc;
                float v = 0.f;
                if (q >= 0 && k >= 0 && k <= q) v = Sb[(size_t)q * SS + k];
                Ssh[rr * S_LD + cc] = v;
            }
        }
        // stage V chunk 64 x 128 -> hi/lo
        for (int i = tid; i < 64 * 32; i += 256) {
            const int kr = i >> 5, c = (i & 31) * 4;
            float4 v = *(const float4*)&Vb[(size_t)(kc + kr) * DD + c];
            split_store4(&Vh[kr * PV_LDV + c], &Vl[kr * PV_LDV + c], v);
        }
        __syncthreads();

        // conv (weights pre-scaled) -> exp (MUFU) -> split-bf16 P
        {
            float out[16] = {};
            #pragma unroll
            for (int dq = 0; dq < 6; dq++) {
                float win[28];
                const float* srow = &Ssh[(pr + dq) * S_LD + pc];
                #pragma unroll
                for (int t4 = 0; t4 < 7; t4++)
                    *(float4*)&win[t4 * 4] = *(const float4*)&srow[t4 * 4];
                #pragma unroll
                for (int dk = 0; dk < 11; dk++) {
                    float w = ws[dq * 11 + dk];
                    #pragma unroll
                    for (int j = 0; j < 16; j++) out[j] += w * win[j + dk];
                }
            }
            #pragma unroll
            for (int j4 = 0; j4 < 4; j4++) {
                const int kbase = kc + pc + j4 * 4;
                float e0 = (kbase + 0 <= pq) ? __expf(out[j4*4+0]) : 0.f;
                float e1 = (kbase + 1 <= pq) ? __expf(out[j4*4+1]) : 0.f;
                float e2 = (kbase + 2 <= pq) ? __expf(out[j4*4+2]) : 0.f;
                float e3 = (kbase + 3 <= pq) ? __expf(out[j4*4+3]) : 0.f;
                psum += (e0 + e1) + (e2 + e3);
                split_store4(&Ph[pr * PV_LDP + pc + j4 * 4],
                             &Pl[pr * PV_LDP + pc + j4 * 4],
                             make_float4(e0, e1, e2, e3));
            }
        }
        __syncthreads();

        // 3-term HMMA: acc += Phi*Vhi + Phi*Vlo + Plo*Vhi
        #pragma unroll
        for (int ks = 0; ks < 4; ks++) {
            const int kb = ks * 16;
            uint32_t ah[2][4], al[2][4];
            #pragma unroll
            for (int mi = 0; mi < 2; mi++) {
                uint32_t aH = smem_u32(&Ph[(m0 + mi * 16 + lrow) * PV_LDP + kb + lgrp * 8]);
                LDMATRIX_X4(ah[mi][0], ah[mi][1], ah[mi][2], ah[mi][3], aH);
                uint32_t aL = smem_u32(&Pl[(m0 + mi * 16 + lrow) * PV_LDP + kb + lgrp * 8]);
                LDMATRIX_X4(al[mi][0], al[mi][1], al[mi][2], al[mi][3], aL);
            }
            #pragma unroll
            for (int ng = 0; ng < 2; ng++) {
                const int vrow = kb + (bi & 1) * 8 + brow;
                const int vcol = n0 + ng * 16 + (bi >> 1) * 8;
                uint32_t vh4[4], vl4[4];
                uint32_t bHaddr = smem_u32(&Vh[vrow * PV_LDV + vcol]);
                LDMATRIX_X4_T(vh4[0], vh4[1], vh4[2], vh4[3], bHaddr);
                uint32_t bLaddr = smem_u32(&Vl[vrow * PV_LDV + vcol]);
                LDMATRIX_X4_T(vl4[0], vl4[1], vl4[2], vl4[3], bLaddr);

                #pragma unroll
                for (int mi = 0; mi < 2; mi++) {
                    MMA_BF16(acc[mi][2 * ng],     ah[mi], vh4[0], vh4[1]);
                    MMA_BF16(acc[mi][2 * ng],     ah[mi], vl4[0], vl4[1]);
                    MMA_BF16(acc[mi][2 * ng],     al[mi], vh4[0], vh4[1]);
                    MMA_BF16(acc[mi][2 * ng + 1], ah[mi], vh4[2], vh4[3]);
                    MMA_BF16(acc[mi][2 * ng + 1], ah[mi], vl4[2], vl4[3]);
                    MMA_BF16(acc[mi][2 * ng + 1], al[mi], vh4[2], vh4[3]);
                }
            }
        }
    }

    // partial row sums (quad lanes share row pr)
    psum += __shfl_xor_sync(0xffffffffu, psum, 1);
    psum += __shfl_xor_sync(0xffffffffu, psum, 2);
    if ((tid & 3) == 0) g_spart[sp][bh * SS + q0 + pr] = psum;

    // write unnormalized partial O
    float* Op = g_opart[sp] + (size_t)bh * SS * DD;
    const int g = lane >> 2, t2 = (lane & 3) * 2;
    #pragma unroll
    for (int mi = 0; mi < 2; mi++) {
        const int lr1 = m0 + mi * 16 + g;
        const int lr2 = lr1 + 8;
        #pragma unroll
        for (int nf = 0; nf < 4; nf++) {
            const int col = n0 + nf * 8 + t2;
            *(float2*)&Op[(size_t)(q0 + lr1) * DD + col] =
                make_float2(acc[mi][nf][0], acc[mi][nf][1]);
            *(float2*)&Op[(size_t)(q0 + lr2) * DD + col] =
                make_float2(acc[mi][nf][2], acc[mi][nf][3]);
        }
    }
}

// ---------------------------------------------------------------------------
// Kernel 3: reduce partials and normalize.  O = (sum_s Op_s) / (sum_s rowSum_s)
// ---------------------------------------------------------------------------
__global__ __launch_bounds__(256) void reduce_out(float* __restrict__ O)
{
    const int row = blockIdx.x * 8 + (threadIdx.x >> 5);
    const int lane = threadIdx.x & 31;
    const int q = row & (SS - 1);
    const int ns = ((q >> 6) >> 2) + 1;

    float s = g_spart[0][row];
    if (ns > 1) s += g_spart[1][row];
    if (ns > 2) s += g_spart[2][row];
    if (ns > 3) s += g_spart[3][row];
    const float inv = 1.f / s;

    const size_t base = (size_t)row * DD + lane * 4;
    float4 a = *(const float4*)&g_opart[0][base];
    if (ns > 1) {
        float4 v = *(const float4*)&g_opart[1][base];
        a.x += v.x; a.y += v.y; a.z += v.z; a.w += v.w;
    }
    if (ns > 2) {
        float4 v = *(const float4*)&g_opart[2][base];
        a.x += v.x; a.y += v.y; a.z += v.z; a.w += v.w;
    }
    if (ns > 3) {
        float4 v = *(const float4*)&g_opart[3][base];
        a.x += v.x; a.y += v.y; a.z += v.z; a.w += v.w;
    }
    *(float4*)&O[base] = make_float4(a.x * inv, a.y * inv, a.z * inv, a.w * inv);
}

// ---------------------------------------------------------------------------
extern "C" void kernel_launch(void* const* d_in, const int* in_sizes, int n_in,
                              void* d_out, int out_size)
{
    const float* Q = (const float*)d_in[0];
    const float* K = (const float*)d_in[1];
    const float* V = (const float*)d_in[2];
    const float* W = (const float*)d_in[3];
    float* O = (float*)d_out;

    const int QK_SMEM = 4 * PLANE2 * (int)sizeof(__nv_bfloat16);  // 73728 B
    cudaFuncSetAttribute(qk_gemm_mma, cudaFuncAttributeMaxDynamicSharedMemorySize, QK_SMEM);

    const int PV_SMEM = 69 * S_LD * (int)sizeof(float)
                      + (2 * 64 * PV_LDP + 2 * 64 * PV_LDV) * (int)sizeof(__nv_bfloat16)
                      + 66 * (int)sizeof(float);                  // ~74.4 KB
    cudaFuncSetAttribute(conv_softmax_pv, cudaFuncAttributeMaxDynamicSharedMemorySize, PV_SMEM);

    dim3 g1(8, 8, NBH);
    qk_gemm_mma<<<g1, 256, QK_SMEM>>>(Q, K);

    dim3 g2(40, NBH);
    conv_softmax_pv<<<g2, 256, PV_SMEM>>>(V, W);

    reduce_out<<<NBH * SS / 8, 256>>>(O);
}